// round 12
// baseline (speedup 1.0000x reference)
#include <cuda_runtime.h>
#include <cstdint>
#include <math.h>

#define EPSV 1e-4f
#define NM   3249                    // 57*57 floats per matrix
#define GM   2                       // matrices per block
#define TILE_FLOATS (GM * NM)        // 6498 (25992 B -> stride only 8B aligned!)
#define TMA_BYTES   25984            // 6496 floats, 16B multiple
#define BLOCKS      4096
#define BLK_PER_B   32               // 64 matrices per batch / GM

// Scratch (allocation-free). Counter reset by last arriver -> graph-replay safe.
__device__ float g_a[128 * 64 * 3];
__device__ int   g_cnt[128];

// Shared layout (floats)
#define SM_X_OFF    0        // 6500 floats (6498 + up-to-2 shift)
#define SM_PQ_OFF   6500     // float2[57] = 114 floats (byte off 26000 % 8 == 0)
#define SM_W23_OFF  6614     // 40
#define SM_C_OFF    6654     // 114*3 = 342 per-row partials
#define SM_LAST_OFF 6996     // int flag
#define SM_MBAR_OFF 6998     // 8B mbarrier (6998*4 = 27992 % 8 == 0)
#define SM_FLOATS   7000
#define SM_BYTES    (SM_FLOATS * 4)  // 28000 B -> 8 blocks/SM

__device__ __forceinline__ void mbar_init(unsigned int mbar, unsigned int cnt) {
    asm volatile("mbarrier.init.shared.b64 [%0], %1;" :: "r"(mbar), "r"(cnt) : "memory");
}
__device__ __forceinline__ void mbar_expect_tx(unsigned int mbar, unsigned int bytes) {
    asm volatile("mbarrier.arrive.expect_tx.shared.b64 _, [%0], %1;"
                 :: "r"(mbar), "r"(bytes) : "memory");
}
__device__ __forceinline__ void bulk_copy_g2s(unsigned int sdst, const void* gsrc,
                                              unsigned int bytes, unsigned int mbar) {
    asm volatile("cp.async.bulk.shared::cta.global.mbarrier::complete_tx::bytes "
                 "[%0], [%1], %2, [%3];"
                 :: "r"(sdst), "l"(gsrc), "r"(bytes), "r"(mbar) : "memory");
}
__device__ __forceinline__ void mbar_wait_parity(unsigned int mbar, unsigned int parity) {
    asm volatile(
        "{\n\t"
        ".reg .pred P1;\n\t"
        "WAIT_LOOP_%=:\n\t"
        "mbarrier.try_wait.parity.acquire.cta.shared::cta.b64 P1, [%0], %1, 0x989680;\n\t"
        "@P1 bra.uni WAIT_DONE_%=;\n\t"
        "bra.uni WAIT_LOOP_%=;\n\t"
        "WAIT_DONE_%=:\n\t"
        "}"
        :: "r"(mbar), "r"(parity) : "memory");
}

__global__ void __launch_bounds__(256, 8)
fused_kernel(const float* __restrict__ x,
             const float* __restrict__ W1,
             const float* __restrict__ W2,
             const float* __restrict__ W3,
             const float* __restrict__ lin_w,
             const float* __restrict__ lin_b,
             const float* __restrict__ alpha,
             float* __restrict__ out) {
    extern __shared__ float sm[];
    float*  sm_x   = sm + SM_X_OFF;
    float2* sm_pq  = (float2*)(sm + SM_PQ_OFF);
    float*  sm_w23 = sm + SM_W23_OFF;
    float*  sm_c   = sm + SM_C_OFF;
    int*    sm_last = (int*)(sm + SM_LAST_OFF);

    const int tid = threadIdx.x;
    const int blk = blockIdx.x;                 // 4096 blocks, 2 matrices each
    const float* xg = x + (size_t)blk * TILE_FLOATS;
    // Odd blocks: global base is only 8B aligned. Shift TMA window by 2 floats.
    const int shift = (blk & 1) * 2;            // smem element f lives at sm_x[f+shift]

    unsigned int sbase;
    asm("{ .reg .u64 t; cvta.to.shared.u64 t, %1; cvt.u32.u64 %0, t; }"
        : "=r"(sbase) : "l"(sm));
    const unsigned int mbar_addr = sbase + SM_MBAR_OFF * 4u;

    // --- mbarrier init, then one TMA bulk copy + 2-float manual patch ---
    if (tid == 0) mbar_init(mbar_addr, 1);
    __syncthreads();
    if (tid == 0) {
        // even: copy floats [0,6496) -> sm_x[0..];    src/dst 16B aligned
        // odd:  copy floats [2,6498) -> sm_x[4..];    src = xg+2 (16B), dst = +16B
        mbar_expect_tx(mbar_addr, TMA_BYTES);
        bulk_copy_g2s(sbase + 4u * (2 * shift), xg + shift, TMA_BYTES, mbar_addr);
    }
    if (tid < 2) {
        // even: floats 6496,6497 ; odd: floats 0,1
        int f = shift ? tid : (6496 + tid);
        sm_x[f + shift] = xg[f];                 // visible after __syncthreads below
    }

    // --- P = W1@W2@W3 (hidden under the in-flight copy) ---
    if (tid < 40) {
        int j = tid >> 1, u = tid & 1;
        float s = 0.f;
        #pragma unroll
        for (int k = 0; k < 10; k++) s = fmaf(__ldg(W2 + j * 10 + k), __ldg(W3 + k * 2 + u), s);
        sm_w23[tid] = s;
    }
    __syncthreads();
    if (tid < 114) {
        int i = tid >> 1, u = tid & 1;
        float s = 0.f;
        #pragma unroll
        for (int j = 0; j < 20; j++) s = fmaf(__ldg(W1 + i * 20 + j), sm_w23[j * 2 + u], s);
        ((float*)&sm_pq[i])[u] = s;
    }

    // --- Wait for the tile (HW-sleep try_wait), phase 0 ---
    mbar_wait_parity(mbar_addr, 0);
    __syncthreads();

    // --- Compute: thread t < 114 owns row t (addr = shift + t*57 + k) ---
    if (tid < 114) {
        const float* xr = sm_x + shift + tid * 57;
        float y0 = 0.f, y1 = 0.f;
        #pragma unroll
        for (int k = 0; k < 57; k++) {
            float  vv = xr[k];
            float2 p  = sm_pq[k];                // warp-uniform broadcast
            y0 = fmaf(vv, p.x, y0);
            y1 = fmaf(vv, p.y, y1);
        }
        int m = (tid >= 57);
        float2 pi = sm_pq[tid - 57 * m];
        sm_c[tid * 3 + 0] = pi.x * y0;
        sm_c[tid * 3 + 1] = pi.x * y1;
        sm_c[tid * 3 + 2] = pi.y * y1;
    }
    __syncthreads();

    // --- Finalize: 6 threads each sum 57 partials for (matrix m, component c) ---
    if (tid < 6) {
        int m = tid / 3;
        int comp = tid - 3 * m;
        const float* base = sm_c + (m * 57) * 3 + comp;
        float s = 0.f;
        #pragma unroll
        for (int r = 0; r < 57; r++) s += base[r * 3];
        g_a[(size_t)(GM * blk + m) * 3 + comp] = s;
    }
    __threadfence();
    __syncthreads();

    const int b = blk >> 5;                      // 32 blocks per b
    if (tid == 0) {
        int old = atomicAdd(&g_cnt[b], 1);
        *sm_last = (old == BLK_PER_B - 1);
        if (old == BLK_PER_B - 1) g_cnt[b] = 0;  // reset for graph replay
    }
    __syncthreads();
    if (!*sm_last) return;

    // --- Scan phase (only last-arriving block per b) ---
    __threadfence();                             // acquire
    float* a0 = sm_x;                            // reuse staged region
    float* a1 = sm_x + 64;
    float* a2 = sm_x + 128;
    float* lw = sm_x + 192;                      // 51
    float* lb = sm_x + 243;                      // 17
    if (tid < 64) {
        const float* ab = g_a + ((size_t)b * 64 + tid) * 3;
        a0[tid] = ab[0]; a1[tid] = ab[1]; a2[tid] = ab[2];
    }
    if (tid < 51) lw[tid] = lin_w[tid];
    if (tid < 17) lb[tid] = lin_b[tid];
    __syncthreads();
    if (tid >= 64) return;

    const int t = tid;
    float s  = 1.f / (1.f + expf(-alpha[0]));
    float os = 1.f - s;

    float h00 = 0.f, h01 = 0.f, h11 = 0.f;
    for (int k = 0; k <= t; k++) {
        float mean = 0.5f * (h00 + h11);
        float diff = 0.5f * (h00 - h11);
        float rad  = sqrtf(diff * diff + h01 * h01);
        float r00, r01, r11;
        if (rad > 1e-20f) {
            float l1 = mean + rad, l2 = mean - rad;
            float m1 = fmaxf(l1, EPSV), m2 = fmaxf(l2, EPSV);
            float c1 = (m1 - m2) / (l1 - l2);
            float c0 = m1 - c1 * l1;
            r00 = c1 * h00 + c0;
            r01 = c1 * h01;
            r11 = c1 * h11 + c0;
        } else {
            if (mean >= EPSV) { r00 = h00; r01 = h01; r11 = h11; }
            else              { r00 = EPSV; r01 = 0.f; r11 = EPSV; }
        }
        h00 = fmaf(s, a0[k], os * r00);
        h01 = fmaf(s, a1[k], os * r01);
        h11 = fmaf(s, a2[k], os * r11);
    }

    float mean = 0.5f * (h00 + h11);
    float diff = 0.5f * (h00 - h11);
    float rad  = sqrtf(diff * diff + h01 * h01);
    float l1 = mean + rad, l2 = mean - rad;
    float d  = l1 - l2;
    float c1 = (d > 0.f) ? (log1pf(d / l2) / d) : (1.f / l1);
    float c0 = logf(l2) - c1 * l2;
    float v0 = c1 * h00 + c0;
    float v1 = c1 * h01;
    float v2 = c1 * h11 + c0;

    float* o = out + ((size_t)b * 64 + t) * 17;
    #pragma unroll
    for (int j = 0; j < 17; j++)
        o[j] = fmaf(lw[j * 3], v0, fmaf(lw[j * 3 + 1], v1, fmaf(lw[j * 3 + 2], v2, lb[j])));
}

// ---------------------------------------------------------------------------
extern "C" void kernel_launch(void* const* d_in, const int* in_sizes, int n_in,
                              void* d_out, int out_size) {
    const float* x     = (const float*)d_in[0];  // (128,64,57,57)
    const float* W1    = (const float*)d_in[1];  // (57,20)
    const float* W2    = (const float*)d_in[2];  // (20,10)
    const float* W3    = (const float*)d_in[3];  // (10,2)
    const float* lin_w = (const float*)d_in[4];  // (17,3)
    const float* lin_b = (const float*)d_in[5];  // (17,)
    const float* alpha = (const float*)d_in[6];  // (1,)
    float* out = (float*)d_out;                  // (128,64,17)

    cudaFuncSetAttribute(fused_kernel, cudaFuncAttributeMaxDynamicSharedMemorySize, SM_BYTES);
    fused_kernel<<<BLOCKS, 256, SM_BYTES>>>(x, W1, W2, W3, lin_w, lin_b, alpha, out);
}

// round 13
// speedup vs baseline: 1.0545x; 1.0545x over previous
#include <cuda_runtime.h>
#include <cstdint>
#include <math.h>

#define EPSV 1e-4f
#define NM   3249            // 57*57 floats per matrix
#define GM   4               // matrices per block
#define BLOCKS 2048
#define BLK_PER_B 16

// Scratch (allocation-free). Counter reset by last arriver -> graph-replay safe.
__device__ float g_a[128 * 64 * 3];
__device__ int   g_cnt[128];

__global__ void __launch_bounds__(256)
fused_kernel(const float* __restrict__ x,
             const float* __restrict__ W1,
             const float* __restrict__ W2,
             const float* __restrict__ W3,
             const float* __restrict__ lin_w,
             const float* __restrict__ lin_b,
             const float* __restrict__ alpha,
             float* __restrict__ out) {
    __shared__ float2 sm_pq[57];
    __shared__ float  sm_w23[40];
    __shared__ float  sm_c[228 * 3];
    __shared__ float  sm_scan[260];      // a0|a1|a2 (64 each) + lw(51) + lb(17)
    __shared__ int    sm_last;

    const int tid = threadIdx.x;
    const int blk = blockIdx.x;          // 2048 blocks, 4 matrices each

    // --- P = W1@W2@W3 ---
    if (tid < 40) {
        int j = tid >> 1, u = tid & 1;
        float s = 0.f;
        #pragma unroll
        for (int k = 0; k < 10; k++) s = fmaf(__ldg(W2 + j * 10 + k), __ldg(W3 + k * 2 + u), s);
        sm_w23[tid] = s;
    }
    __syncthreads();
    if (tid < 114) {
        int i = tid >> 1, u = tid & 1;
        float s = 0.f;
        #pragma unroll
        for (int j = 0; j < 20; j++) s = fmaf(__ldg(W1 + i * 20 + j), sm_w23[j * 2 + u], s);
        ((float*)&sm_pq[i])[u] = s;
    }
    __syncthreads();

    // --- Triangle compute: thread t<228 owns (matrix m, row i); reads only k<=i ---
    if (tid < 228) {
        const int m = tid / 57;
        const int i = tid - 57 * m;
        const int g0 = (blk * GM + m) * NM + 57 * i;   // first element of row (< 2^25)
        const int q0 = g0 >> 2;
        const int q1 = (g0 + i) >> 2;
        const float4* xq = (const float4*)x;

        float u0 = 0.f, u1 = 0.f, dd = 0.f;

        // process one aligned quad: elements have k = (q<<2)-g0 + e
        #define PROC(vv, qq)                                                     \
        {                                                                        \
            int rel = ((qq) << 2) - g0;                                          \
            float el[4] = {(vv).x, (vv).y, (vv).z, (vv).w};                      \
            _Pragma("unroll")                                                    \
            for (int e = 0; e < 4; e++) {                                        \
                int k = rel + e;                                                 \
                if ((unsigned)k < (unsigned)i) {                                 \
                    float2 pk = sm_pq[k];                                        \
                    u0 = fmaf(el[e], pk.x, u0);                                  \
                    u1 = fmaf(el[e], pk.y, u1);                                  \
                } else if (k == i) {                                             \
                    dd = el[e];                                                  \
                }                                                                \
            }                                                                    \
        }

        int q = q0;
        for (; q + 1 <= q1; q += 2) {          // pairwise for MLP=2 per lane
            float4 v0 = xq[q];
            float4 v1 = xq[q + 1];
            PROC(v0, q);
            PROC(v1, q + 1);
        }
        if (q <= q1) {
            float4 v0 = xq[q];
            PROC(v0, q);
        }
        #undef PROC

        float2 pi = sm_pq[i];
        sm_c[tid * 3 + 0] = pi.x * (2.f * u0 + dd * pi.x);
        sm_c[tid * 3 + 1] = fmaf(pi.x, u1, fmaf(pi.y, u0, pi.x * pi.y * dd));
        sm_c[tid * 3 + 2] = pi.y * (2.f * u1 + dd * pi.y);
    }
    __syncthreads();

    // --- Finalize: 12 threads each sum 57 partials for (matrix m, component c) ---
    if (tid < 12) {
        int m = tid / 3;
        int comp = tid - 3 * m;
        const float* base = sm_c + (m * 57) * 3 + comp;
        float s = 0.f;
        #pragma unroll
        for (int r = 0; r < 57; r++) s += base[r * 3];
        g_a[(size_t)(GM * blk + m) * 3 + comp] = s;
    }
    __threadfence();
    __syncthreads();

    const int b = blk >> 4;                      // 16 blocks per batch
    if (tid == 0) {
        int old = atomicAdd(&g_cnt[b], 1);
        sm_last = (old == BLK_PER_B - 1);
        if (old == BLK_PER_B - 1) g_cnt[b] = 0;  // reset for graph replay
    }
    __syncthreads();
    if (!sm_last) return;

    // --- Scan phase (only last-arriving block per b) ---
    __threadfence();                             // acquire
    float* a0 = sm_scan;
    float* a1 = sm_scan + 64;
    float* a2 = sm_scan + 128;
    float* lw = sm_scan + 192;                   // 51
    float* lb = sm_scan + 243;                   // 17
    if (tid < 64) {
        const float* ab = g_a + ((size_t)b * 64 + tid) * 3;
        a0[tid] = ab[0]; a1[tid] = ab[1]; a2[tid] = ab[2];
    }
    if (tid < 51) lw[tid] = lin_w[tid];
    if (tid < 17) lb[tid] = lin_b[tid];
    __syncthreads();
    if (tid >= 64) return;

    const int t = tid;
    float s  = 1.f / (1.f + expf(-alpha[0]));
    float os = 1.f - s;

    float h00 = 0.f, h01 = 0.f, h11 = 0.f;
    for (int k = 0; k <= t; k++) {
        float mean = 0.5f * (h00 + h11);
        float diff = 0.5f * (h00 - h11);
        float rad  = sqrtf(diff * diff + h01 * h01);
        float r00, r01, r11;
        if (rad > 1e-20f) {
            float l1 = mean + rad, l2 = mean - rad;
            float m1 = fmaxf(l1, EPSV), m2 = fmaxf(l2, EPSV);
            float c1 = (m1 - m2) / (l1 - l2);
            float c0 = m1 - c1 * l1;
            r00 = c1 * h00 + c0;
            r01 = c1 * h01;
            r11 = c1 * h11 + c0;
        } else {
            if (mean >= EPSV) { r00 = h00; r01 = h01; r11 = h11; }
            else              { r00 = EPSV; r01 = 0.f; r11 = EPSV; }
        }
        h00 = fmaf(s, a0[k], os * r00);
        h01 = fmaf(s, a1[k], os * r01);
        h11 = fmaf(s, a2[k], os * r11);
    }

    float mean = 0.5f * (h00 + h11);
    float diff = 0.5f * (h00 - h11);
    float rad  = sqrtf(diff * diff + h01 * h01);
    float l1 = mean + rad, l2 = mean - rad;
    float d  = l1 - l2;
    float c1 = (d > 0.f) ? (log1pf(d / l2) / d) : (1.f / l1);
    float c0 = logf(l2) - c1 * l2;
    float v0 = c1 * h00 + c0;
    float v1 = c1 * h01;
    float v2 = c1 * h11 + c0;

    float* o = out + ((size_t)b * 64 + t) * 17;
    #pragma unroll
    for (int j = 0; j < 17; j++)
        o[j] = fmaf(lw[j * 3], v0, fmaf(lw[j * 3 + 1], v1, fmaf(lw[j * 3 + 2], v2, lb[j])));
}

// ---------------------------------------------------------------------------
extern "C" void kernel_launch(void* const* d_in, const int* in_sizes, int n_in,
                              void* d_out, int out_size) {
    const float* x     = (const float*)d_in[0];  // (128,64,57,57)
    const float* W1    = (const float*)d_in[1];  // (57,20)
    const float* W2    = (const float*)d_in[2];  // (20,10)
    const float* W3    = (const float*)d_in[3];  // (10,2)
    const float* lin_w = (const float*)d_in[4];  // (17,3)
    const float* lin_b = (const float*)d_in[5];  // (17,)
    const float* alpha = (const float*)d_in[6];  // (1,)
    float* out = (float*)d_out;                  // (128,64,17)

    fused_kernel<<<BLOCKS, 256>>>(x, W1, W2, W3, lin_w, lin_b, alpha, out);
}

// round 14
// speedup vs baseline: 1.1367x; 1.0780x over previous
#include <cuda_runtime.h>
#include <cstdint>
#include <math.h>

#define EPSV 1e-4f
#define NM   3249           // 57*57 floats per matrix
#define GM   4              // matrices per block
#define TILE_BYTES (GM * NM * 4)   // 51984, multiple of 16

// Scratch (allocation-free). Counter reset by last arriver -> graph-replay safe.
__device__ float g_a[128 * 64 * 3];
__device__ int   g_cnt[128];

// Shared layout (floats)
#define SM_X_OFF    0        // 12996: 4 staged matrices
#define SM_PQ_OFF   12996    // float2[57] = 114 floats
#define SM_W23_OFF  13110    // 40
#define SM_C_OFF    13150    // 228*3 per-row partials = 684
#define SM_LAST_OFF 13834    // int flag
#define SM_MBAR_OFF 13836    // 8B mbarrier (13836*4 % 8 == 0)
#define SM_FLOATS   13840
#define SM_BYTES    (SM_FLOATS * 4)

__device__ __forceinline__ void mbar_init(unsigned int mbar, unsigned int cnt) {
    asm volatile("mbarrier.init.shared.b64 [%0], %1;" :: "r"(mbar), "r"(cnt) : "memory");
}
__device__ __forceinline__ void mbar_expect_tx(unsigned int mbar, unsigned int bytes) {
    asm volatile("mbarrier.arrive.expect_tx.shared.b64 _, [%0], %1;"
                 :: "r"(mbar), "r"(bytes) : "memory");
}
// Bulk copy with L2 evict_last policy: keeps x resident in L2 across graph replays.
__device__ __forceinline__ void bulk_copy_g2s_persist(unsigned int sdst, const void* gsrc,
                                                      unsigned int bytes, unsigned int mbar) {
    asm volatile(
        "{\n\t"
        ".reg .b64 pol;\n\t"
        "createpolicy.fractional.L2::evict_last.b64 pol, 1.0;\n\t"
        "cp.async.bulk.shared::cta.global.mbarrier::complete_tx::bytes.L2::cache_hint "
        "[%0], [%1], %2, [%3], pol;\n\t"
        "}"
        :: "r"(sdst), "l"(gsrc), "r"(bytes), "r"(mbar) : "memory");
}
__device__ __forceinline__ void mbar_wait_parity(unsigned int mbar, unsigned int parity) {
    asm volatile(
        "{\n\t"
        ".reg .pred P1;\n\t"
        "WAIT_LOOP_%=:\n\t"
        "mbarrier.try_wait.parity.acquire.cta.shared::cta.b64 P1, [%0], %1, 0x989680;\n\t"
        "@P1 bra.uni WAIT_DONE_%=;\n\t"
        "bra.uni WAIT_LOOP_%=;\n\t"
        "WAIT_DONE_%=:\n\t"
        "}"
        :: "r"(mbar), "r"(parity) : "memory");
}

__global__ void __launch_bounds__(512, 4)
fused_kernel(const float* __restrict__ x,
             const float* __restrict__ W1,
             const float* __restrict__ W2,
             const float* __restrict__ W3,
             const float* __restrict__ lin_w,
             const float* __restrict__ lin_b,
             const float* __restrict__ alpha,
             float* __restrict__ out) {
    extern __shared__ float sm[];
    float*  sm_x   = sm + SM_X_OFF;
    float2* sm_pq  = (float2*)(sm + SM_PQ_OFF);
    float*  sm_w23 = sm + SM_W23_OFF;
    float*  sm_c   = sm + SM_C_OFF;
    int*    sm_last = (int*)(sm + SM_LAST_OFF);

    const int tid = threadIdx.x;
    const int blk = blockIdx.x;                 // 2048 blocks, 4 matrices each
    const float* xg = x + (size_t)blk * (GM * NM);

    unsigned int sbase;
    asm("{ .reg .u64 t; cvta.to.shared.u64 t, %1; cvt.u32.u64 %0, t; }"
        : "=r"(sbase) : "l"(sm));
    const unsigned int sx_addr   = sbase + SM_X_OFF * 4u;
    const unsigned int mbar_addr = sbase + SM_MBAR_OFF * 4u;

    // --- mbarrier init, then one TMA bulk copy (L2 evict_last) for the 52KB tile ---
    if (tid == 0) mbar_init(mbar_addr, 1);
    __syncthreads();
    if (tid == 0) {
        mbar_expect_tx(mbar_addr, TILE_BYTES);
        bulk_copy_g2s_persist(sx_addr, xg, TILE_BYTES, mbar_addr);
    }

    // --- P = W1@W2@W3 (hidden under the in-flight bulk copy) ---
    if (tid < 40) {
        int j = tid >> 1, u = tid & 1;
        float s = 0.f;
        #pragma unroll
        for (int k = 0; k < 10; k++) s = fmaf(__ldg(W2 + j * 10 + k), __ldg(W3 + k * 2 + u), s);
        sm_w23[tid] = s;
    }
    __syncthreads();
    if (tid < 114) {
        int i = tid >> 1, u = tid & 1;
        float s = 0.f;
        #pragma unroll
        for (int j = 0; j < 20; j++) s = fmaf(__ldg(W1 + i * 20 + j), sm_w23[j * 2 + u], s);
        ((float*)&sm_pq[i])[u] = s;
    }

    // --- Wait for the tile (HW-sleep try_wait), phase 0 ---
    mbar_wait_parity(mbar_addr, 0);
    __syncthreads();

    // --- Compute: thread t owns global row t (addr = t*57 + k), bank stride 25 ---
    if (tid < 228) {
        const float* xr = sm_x + tid * 57;
        float y0 = 0.f, y1 = 0.f;
        #pragma unroll
        for (int k = 0; k < 57; k++) {
            float  vv = xr[k];
            float2 p  = sm_pq[k];                // warp-uniform broadcast
            y0 = fmaf(vv, p.x, y0);
            y1 = fmaf(vv, p.y, y1);
        }
        int m = tid / 57;
        float2 pi = sm_pq[tid - 57 * m];
        sm_c[tid * 3 + 0] = pi.x * y0;
        sm_c[tid * 3 + 1] = pi.x * y1;
        sm_c[tid * 3 + 2] = pi.y * y1;
    }
    __syncthreads();

    // --- Finalize: 12 threads each sum 57 partials for (matrix m, component c) ---
    if (tid < 12) {
        int m = tid / 3;
        int comp = tid - 3 * m;
        const float* base = sm_c + (m * 57) * 3 + comp;
        float s = 0.f;
        #pragma unroll
        for (int r = 0; r < 57; r++) s += base[r * 3];
        g_a[(size_t)(GM * blk + m) * 3 + comp] = s;
    }
    __threadfence();
    __syncthreads();

    const int b = blk >> 4;                      // 16 blocks per b
    if (tid == 0) {
        int old = atomicAdd(&g_cnt[b], 1);
        *sm_last = (old == 15);
        if (old == 15) g_cnt[b] = 0;             // reset for graph replay
    }
    __syncthreads();
    if (!*sm_last) return;

    // --- Scan phase (only last-arriving block per b) ---
    __threadfence();                             // acquire
    float* a0 = sm_x;                            // reuse staged region
    float* a1 = sm_x + 64;
    float* a2 = sm_x + 128;
    float* lw = sm_x + 192;                      // 51
    float* lb = sm_x + 243;                      // 17
    if (tid < 64) {
        const float* ab = g_a + ((size_t)b * 64 + tid) * 3;
        a0[tid] = ab[0]; a1[tid] = ab[1]; a2[tid] = ab[2];
    }
    if (tid < 51) lw[tid] = lin_w[tid];
    if (tid < 17) lb[tid] = lin_b[tid];
    __syncthreads();
    if (tid >= 64) return;

    const int t = tid;
    float s  = 1.f / (1.f + expf(-alpha[0]));
    float os = 1.f - s;

    float h00 = 0.f, h01 = 0.f, h11 = 0.f;
    for (int k = 0; k <= t; k++) {
        float mean = 0.5f * (h00 + h11);
        float diff = 0.5f * (h00 - h11);
        float rad  = sqrtf(diff * diff + h01 * h01);
        float r00, r01, r11;
        if (rad > 1e-20f) {
            float l1 = mean + rad, l2 = mean - rad;
            float m1 = fmaxf(l1, EPSV), m2 = fmaxf(l2, EPSV);
            float c1 = (m1 - m2) / (l1 - l2);
            float c0 = m1 - c1 * l1;
            r00 = c1 * h00 + c0;
            r01 = c1 * h01;
            r11 = c1 * h11 + c0;
        } else {
            if (mean >= EPSV) { r00 = h00; r01 = h01; r11 = h11; }
            else              { r00 = EPSV; r01 = 0.f; r11 = EPSV; }
        }
        h00 = fmaf(s, a0[k], os * r00);
        h01 = fmaf(s, a1[k], os * r01);
        h11 = fmaf(s, a2[k], os * r11);
    }

    float mean = 0.5f * (h00 + h11);
    float diff = 0.5f * (h00 - h11);
    float rad  = sqrtf(diff * diff + h01 * h01);
    float l1 = mean + rad, l2 = mean - rad;
    float d  = l1 - l2;
    float c1 = (d > 0.f) ? (log1pf(d / l2) / d) : (1.f / l1);
    float c0 = logf(l2) - c1 * l2;
    float v0 = c1 * h00 + c0;
    float v1 = c1 * h01;
    float v2 = c1 * h11 + c0;

    float* o = out + ((size_t)b * 64 + t) * 17;
    #pragma unroll
    for (int j = 0; j < 17; j++)
        o[j] = fmaf(lw[j * 3], v0, fmaf(lw[j * 3 + 1], v1, fmaf(lw[j * 3 + 2], v2, lb[j])));
}

// ---------------------------------------------------------------------------
extern "C" void kernel_launch(void* const* d_in, const int* in_sizes, int n_in,
                              void* d_out, int out_size) {
    const float* x     = (const float*)d_in[0];  // (128,64,57,57)
    const float* W1    = (const float*)d_in[1];  // (57,20)
    const float* W2    = (const float*)d_in[2];  // (20,10)
    const float* W3    = (const float*)d_in[3];  // (10,2)
    const float* lin_w = (const float*)d_in[4];  // (17,3)
    const float* lin_b = (const float*)d_in[5];  // (17,)
    const float* alpha = (const float*)d_in[6];  // (1,)
    float* out = (float*)d_out;                  // (128,64,17)

    cudaFuncSetAttribute(fused_kernel, cudaFuncAttributeMaxDynamicSharedMemorySize, SM_BYTES);
    fused_kernel<<<2048, 512, SM_BYTES>>>(x, W1, W2, W3, lin_w, lin_b, alpha, out);
}

// round 15
// speedup vs baseline: 1.1823x; 1.0401x over previous
#include <cuda_runtime.h>
#include <cstdint>
#include <math.h>

#define EPSV 1e-4f
#define NM   3249            // 57*57 floats per matrix
#define WPB  8               // warps (=matrices) per block
#define BLOCKS 1024          // 8192 matrices / 8
#define BLK_PER_B 8          // 64 matrices per batch / 8 per block

// Scratch (allocation-free). Counter reset by last arriver -> graph-replay safe.
__device__ float g_a[128 * 64 * 3];
__device__ int   g_cnt[128];

__global__ void __launch_bounds__(256, 8)
fused_kernel(const float* __restrict__ x,
             const float* __restrict__ W1,
             const float* __restrict__ W2,
             const float* __restrict__ W3,
             const float* __restrict__ lin_w,
             const float* __restrict__ lin_b,
             const float* __restrict__ alpha,
             float* __restrict__ out) {
    __shared__ float2 sm_pq[57];
    __shared__ float  sm_w23[40];
    __shared__ float  sm_scan[260];     // a0|a1|a2 (64 each) + lw(51) + lb(17)
    __shared__ int    sm_last;

    const int tid  = threadIdx.x;
    const int wid  = tid >> 5;
    const int lane = tid & 31;
    const int blk  = blockIdx.x;

    // --- P = W1@W2@W3 into sm_pq ---
    if (tid < 40) {
        int j = tid >> 1, u = tid & 1;
        float s = 0.f;
        #pragma unroll
        for (int k = 0; k < 10; k++) s = fmaf(__ldg(W2 + j * 10 + k), __ldg(W3 + k * 2 + u), s);
        sm_w23[tid] = s;
    }
    __syncthreads();
    if (tid < 114) {
        int i = tid >> 1, u = tid & 1;
        float s = 0.f;
        #pragma unroll
        for (int j = 0; j < 20; j++) s = fmaf(__ldg(W1 + i * 20 + j), sm_w23[j * 2 + u], s);
        ((float*)&sm_pq[i])[u] = s;
    }
    __syncthreads();

    // --- Per-warp matrix: c = P^T X P with register-resident column weights ---
    const int gm = blk * WPB + wid;              // matrix id 0..8191
    const float* xm = x + (size_t)gm * NM;

    const float2 pk0 = sm_pq[lane];              // weight for k = lane
    const bool   hi  = (lane < 25);
    const float2 pk1 = hi ? sm_pq[32 + lane] : make_float2(0.f, 0.f);
    const int    off1 = hi ? (32 + lane) : 0;    // safe address (value masked by pk1=0)

    float c00 = 0.f, c01 = 0.f, c11 = 0.f;

    #define ROW(i_)                                                   \
    {                                                                 \
        const float* r = xm + 57 * (i_);                              \
        float a0 = r[lane];                                           \
        float a1 = r[off1];                                           \
        float2 pi = sm_pq[(i_)];                                      \
        float u = fmaf(a1, pk1.x, a0 * pk0.x);                        \
        float v = fmaf(a1, pk1.y, a0 * pk0.y);                        \
        c00 = fmaf(pi.x, u, c00);                                     \
        c01 = fmaf(pi.x, v, c01);                                     \
        c11 = fmaf(pi.y, v, c11);                                     \
    }

    #pragma unroll 4
    for (int i = 0; i < 56; i += 2) {            // 2-row software pipeline (MLP=4)
        ROW(i);
        ROW(i + 1);
    }
    ROW(56);
    #undef ROW

    // warp reduction (X symmetric -> c01 total is well-defined)
    #pragma unroll
    for (int o = 16; o; o >>= 1) {
        c00 += __shfl_xor_sync(0xFFFFFFFFu, c00, o);
        c01 += __shfl_xor_sync(0xFFFFFFFFu, c01, o);
        c11 += __shfl_xor_sync(0xFFFFFFFFu, c11, o);
    }
    if (lane == 0) {
        float* o = g_a + (size_t)gm * 3;
        o[0] = c00; o[1] = c01; o[2] = c11;
    }
    __threadfence();
    __syncthreads();

    const int b = blk >> 3;                      // 8 blocks per batch
    if (tid == 0) {
        int old = atomicAdd(&g_cnt[b], 1);
        sm_last = (old == BLK_PER_B - 1);
        if (old == BLK_PER_B - 1) g_cnt[b] = 0;  // reset for graph replay
    }
    __syncthreads();
    if (!sm_last) return;

    // --- Scan phase (only last-arriving block per b) ---
    __threadfence();                             // acquire
    float* a0 = sm_scan;
    float* a1 = sm_scan + 64;
    float* a2 = sm_scan + 128;
    float* lw = sm_scan + 192;                   // 51
    float* lb = sm_scan + 243;                   // 17
    if (tid < 64) {
        const float* ab = g_a + ((size_t)b * 64 + tid) * 3;
        a0[tid] = ab[0]; a1[tid] = ab[1]; a2[tid] = ab[2];
    }
    if (tid < 51) lw[tid] = lin_w[tid];
    if (tid < 17) lb[tid] = lin_b[tid];
    __syncthreads();
    if (tid >= 64) return;

    const int t = tid;
    float s  = 1.f / (1.f + expf(-alpha[0]));
    float os = 1.f - s;

    float h00 = 0.f, h01 = 0.f, h11 = 0.f;
    for (int k = 0; k <= t; k++) {
        float mean = 0.5f * (h00 + h11);
        float diff = 0.5f * (h00 - h11);
        float rad  = sqrtf(diff * diff + h01 * h01);
        float r00, r01, r11;
        if (rad > 1e-20f) {
            float l1 = mean + rad, l2 = mean - rad;
            float m1 = fmaxf(l1, EPSV), m2 = fmaxf(l2, EPSV);
            float c1 = (m1 - m2) / (l1 - l2);
            float c0 = m1 - c1 * l1;
            r00 = c1 * h00 + c0;
            r01 = c1 * h01;
            r11 = c1 * h11 + c0;
        } else {
            if (mean >= EPSV) { r00 = h00; r01 = h01; r11 = h11; }
            else              { r00 = EPSV; r01 = 0.f; r11 = EPSV; }
        }
        h00 = fmaf(s, a0[k], os * r00);
        h01 = fmaf(s, a1[k], os * r01);
        h11 = fmaf(s, a2[k], os * r11);
    }

    float mean = 0.5f * (h00 + h11);
    float diff = 0.5f * (h00 - h11);
    float rad  = sqrtf(diff * diff + h01 * h01);
    float l1 = mean + rad, l2 = mean - rad;
    float d  = l1 - l2;
    float c1 = (d > 0.f) ? (log1pf(d / l2) / d) : (1.f / l1);
    float c0 = logf(l2) - c1 * l2;
    float v0 = c1 * h00 + c0;
    float v1 = c1 * h01;
    float v2 = c1 * h11 + c0;

    float* o = out + ((size_t)b * 64 + t) * 17;
    #pragma unroll
    for (int j = 0; j < 17; j++)
        o[j] = fmaf(lw[j * 3], v0, fmaf(lw[j * 3 + 1], v1, fmaf(lw[j * 3 + 2], v2, lb[j])));
}

// ---------------------------------------------------------------------------
extern "C" void kernel_launch(void* const* d_in, const int* in_sizes, int n_in,
                              void* d_out, int out_size) {
    const float* x     = (const float*)d_in[0];  // (128,64,57,57)
    const float* W1    = (const float*)d_in[1];  // (57,20)
    const float* W2    = (const float*)d_in[2];  // (20,10)
    const float* W3    = (const float*)d_in[3];  // (10,2)
    const float* lin_w = (const float*)d_in[4];  // (17,3)
    const float* lin_b = (const float*)d_in[5];  // (17,)
    const float* alpha = (const float*)d_in[6];  // (1,)
    float* out = (float*)d_out;                  // (128,64,17)

    fused_kernel<<<BLOCKS, 256>>>(x, W1, W2, W3, lin_w, lin_b, alpha, out);
}